// round 16
// baseline (speedup 1.0000x reference)
#include <cuda_runtime.h>

#define NN 500000
#define BB 4096
#define DD 256
#define DL 10
#define TH 768

typedef unsigned long long ull;

// ---------------- f32x2 packed-math helpers (sm_103a FFMA2 path) ----------------
__device__ __forceinline__ ull f2pack(float lo, float hi) {
    ull r; asm("mov.b64 %0, {%1, %2};" : "=l"(r) : "f"(lo), "f"(hi)); return r;
}
__device__ __forceinline__ void f2unpack(ull v, float& lo, float& hi) {
    asm("mov.b64 {%0, %1}, %2;" : "=f"(lo), "=f"(hi) : "l"(v));
}
__device__ __forceinline__ ull f2fma(ull a, ull b, ull c) {
    ull d; asm("fma.rn.f32x2 %0, %1, %2, %3;" : "=l"(d) : "l"(a), "l"(b), "l"(c)); return d;
}
__device__ __forceinline__ ull f2mul(ull a, ull b) {
    ull d; asm("mul.rn.f32x2 %0, %1, %2;" : "=l"(d) : "l"(a), "l"(b)); return d;
}

// ---------------- device scratch (no allocation allowed) ----------------
__device__ int   d_segstart[BB + 1];
__device__ float d_c1[BB * DL];          // graph-half of layer1 + b_l1, per graph
__device__ float d_Sdiv[BB * DD];        // softmax-weighted mean of node feats per graph
__device__ float d_has[BB];              // 1 if segment nonempty else 0
__device__ float d_Wcomb[TH * DD];       // W_ih @ W_msg
__device__ float d_bmsgih[TH];           // W_ih @ b_msg
__device__ float d_gi[(size_t)BB * TH];
__device__ float d_gh[(size_t)BB * TH];

// ---------------- K1: segment boundaries (ids are sorted, int32) ----------------
__global__ void k_segstart(const int* __restrict__ seg) {
    int g = blockIdx.x * blockDim.x + threadIdx.x;
    if (g > BB) return;
    int lo = 0, hi = NN;
    while (lo < hi) {
        int mid = (lo + hi) >> 1;
        if (seg[mid] < g) lo = mid + 1; else hi = mid;
    }
    d_segstart[g] = lo;
}

// ---------------- K2: c1[g][j] = W_l1[j, :256] . relu(gf[g]) + b_l1[j] ----------------
// Atomic-free: warp per graph, butterfly reduction.
__global__ void __launch_bounds__(256) k_c1(const float* __restrict__ gf,
                                            const float* __restrict__ Wl1,
                                            const float* __restrict__ bl1) {
    __shared__ float Wg[DL][260];    // graph-half of W_l1 (columns 0..255)
    __shared__ float bl[DL];
    int tid = threadIdx.x;
    int wo = tid >> 5, lane = tid & 31;
    for (int i = tid; i < DL * DD; i += 256) {
        int j = i >> 8, f = i & 255;
        Wg[j][f] = Wl1[j * (2 * DD) + f];
    }
    if (tid < DL) bl[tid] = bl1[tid];
    __syncthreads();

    int g = blockIdx.x * 8 + wo;
    const float4* gp = (const float4*)(gf + (size_t)g * DD);
    float4 a = gp[lane], b = gp[32 + lane];
    a.x = fmaxf(a.x, 0.f); a.y = fmaxf(a.y, 0.f); a.z = fmaxf(a.z, 0.f); a.w = fmaxf(a.w, 0.f);
    b.x = fmaxf(b.x, 0.f); b.y = fmaxf(b.y, 0.f); b.z = fmaxf(b.z, 0.f); b.w = fmaxf(b.w, 0.f);

    float p[DL];
#pragma unroll
    for (int j = 0; j < DL; j++) {
        float4 w0 = *(const float4*)&Wg[j][lane * 4];
        float4 w1 = *(const float4*)&Wg[j][128 + lane * 4];
        float s = w0.x * a.x;
        s = fmaf(w0.y, a.y, s); s = fmaf(w0.z, a.z, s); s = fmaf(w0.w, a.w, s);
        s = fmaf(w1.x, b.x, s); s = fmaf(w1.y, b.y, s);
        s = fmaf(w1.z, b.z, s); s = fmaf(w1.w, b.w, s);
        p[j] = s;
    }
#pragma unroll
    for (int off = 16; off; off >>= 1) {
#pragma unroll
        for (int j = 0; j < DL; j++) p[j] += __shfl_xor_sync(0xffffffffu, p[j], off);
    }
    if (lane == 0) {
#pragma unroll
        for (int j = 0; j < DL; j++) d_c1[g * DL + j] = p[j] + bl[j];
    }
}

// ---------------- K3: W_comb = W_ih @ W_msg  (768x256) ----------------
__global__ void k_wcomb(const float* __restrict__ Wih, const float* __restrict__ Wmsg) {
    __shared__ float wih_s[4][DD];
    int o0 = blockIdx.x * 4, t = threadIdx.x;
#pragma unroll
    for (int oo = 0; oo < 4; oo++) wih_s[oo][t] = Wih[(o0 + oo) * DD + t];
    __syncthreads();
    float a0 = 0.f, a1 = 0.f, a2 = 0.f, a3 = 0.f;
    for (int m = 0; m < DD; m++) {
        float wm = Wmsg[m * DD + t];
        a0 = fmaf(wih_s[0][m], wm, a0);
        a1 = fmaf(wih_s[1][m], wm, a1);
        a2 = fmaf(wih_s[2][m], wm, a2);
        a3 = fmaf(wih_s[3][m], wm, a3);
    }
    d_Wcomb[(o0 + 0) * DD + t] = a0;
    d_Wcomb[(o0 + 1) * DD + t] = a1;
    d_Wcomb[(o0 + 2) * DD + t] = a2;
    d_Wcomb[(o0 + 3) * DD + t] = a3;
}

// ---------------- K3b: bmsg_ih[o] = W_ih[o] . b_msg ----------------
__global__ void k_bmsgih(const float* __restrict__ Wih, const float* __restrict__ bmsg) {
    __shared__ float s;
    int o = blockIdx.x, t = threadIdx.x;
    if (t == 0) s = 0.f;
    __syncthreads();
    float v = Wih[o * DD + t] * bmsg[t];
#pragma unroll
    for (int off = 16; off; off >>= 1) v += __shfl_xor_sync(0xffffffffu, v, off);
    if ((t & 31) == 0) atomicAdd(&s, v);
    __syncthreads();
    if (t == 0) d_bmsgih[o] = s;
}

// ---------------- K4: fused attention + weighted segment mean (R13, UNCHANGED) ----------------
__global__ void __launch_bounds__(128) k_attn(const float* __restrict__ xf,
                                              const float* __restrict__ Wl1,
                                              const float* __restrict__ Wl2,
                                              const float* __restrict__ bl2) {
    __shared__ float Ws[DL][260];     // node-half of W_l1 (10x256, padded)
    __shared__ float c_s[DL];
    __shared__ float w2_s[DL];
    __shared__ float s_Z[4];
    __shared__ float4 s_acc[4][64];   // [warp][feature-float4]
    int tid = threadIdx.x;
    int wo = tid >> 5, lane = tid & 31;
    int g = blockIdx.x;

    for (int i = tid; i < DL * DD; i += 128) {
        int j = i >> 8, f = i & 255;
        Ws[j][f] = Wl1[j * (2 * DD) + DD + f];
    }
    if (tid < DL) { c_s[tid] = d_c1[g * DL + tid]; w2_s[tid] = Wl2[tid]; }
    __syncthreads();

    float c1r[DL], w2r[DL];
#pragma unroll
    for (int j = 0; j < DL; j++) { c1r[j] = c_s[j]; w2r[j] = w2_s[j]; }
    float b2v = bl2[0];

    int i0 = d_segstart[g], i1 = d_segstart[g + 1];

    ull acc[4] = {0ull, 0ull, 0ull, 0ull};   // packed 8-feature accumulator
    float Z = 0.f;
    int nsel = ((lane >> 3) & 1) * 2 + ((lane >> 4) & 1);  // 0..7->A 16..23->B 8..15->C 24..31->D

    ull X0[4][4], X1[4][4];   // ping-pong groups of 4 nodes, 8 packed floats each

#define LDGROUP(XR, BASE) do {                                                 \
    _Pragma("unroll")                                                          \
    for (int s_ = 0; s_ < 4; s_++) {                                           \
        int idx_ = (BASE) + s_;                                                \
        if (idx_ < i1) {                                                       \
            const ulonglong2* rp_ = (const ulonglong2*)(xf + (size_t)idx_ * DD); \
            ulonglong2 u_ = rp_[lane];                                         \
            ulonglong2 v_ = rp_[32 + lane];                                    \
            XR[s_][0] = u_.x; XR[s_][1] = u_.y;                                \
            XR[s_][2] = v_.x; XR[s_][3] = v_.y;                                \
        } else {                                                               \
            XR[s_][0] = 0ull; XR[s_][1] = 0ull;                                \
            XR[s_][2] = 0ull; XR[s_][3] = 0ull;                                \
        }                                                                      \
    } } while (0)

    auto process = [&](const ull (*X)[4], int base) {
        float lg = b2v;
#pragma unroll
        for (int j = 0; j < DL; j++) {
            ulonglong2 wv0 = *(const ulonglong2*)&Ws[j][lane * 4];
            ulonglong2 wv1 = *(const ulonglong2*)&Ws[j][128 + lane * 4];
            float pA, pB, pC, pD;
            {
                ull t0 = f2fma(wv0.y, X[0][1], f2mul(wv0.x, X[0][0]));
                t0 = f2fma(wv1.x, X[0][2], t0);
                t0 = f2fma(wv1.y, X[0][3], t0);
                float lo, hi; f2unpack(t0, lo, hi); pA = lo + hi;
                ull t1 = f2fma(wv0.y, X[1][1], f2mul(wv0.x, X[1][0]));
                t1 = f2fma(wv1.x, X[1][2], t1);
                t1 = f2fma(wv1.y, X[1][3], t1);
                f2unpack(t1, lo, hi); pB = lo + hi;
                ull t2 = f2fma(wv0.y, X[2][1], f2mul(wv0.x, X[2][0]));
                t2 = f2fma(wv1.x, X[2][2], t2);
                t2 = f2fma(wv1.y, X[2][3], t2);
                f2unpack(t2, lo, hi); pC = lo + hi;
                ull t3 = f2fma(wv0.y, X[3][1], f2mul(wv0.x, X[3][0]));
                t3 = f2fma(wv1.x, X[3][2], t3);
                t3 = f2fma(wv1.y, X[3][3], t3);
                f2unpack(t3, lo, hi); pD = lo + hi;
            }
            float ra = pA + __shfl_xor_sync(0xffffffffu, pA, 16);
            float rb = pB + __shfl_xor_sync(0xffffffffu, pB, 16);
            float rc = pC + __shfl_xor_sync(0xffffffffu, pC, 16);
            float rd = pD + __shfl_xor_sync(0xffffffffu, pD, 16);
            float v1 = (lane & 16) ? rb : ra;
            float v2 = (lane & 16) ? rd : rc;
            v1 += __shfl_xor_sync(0xffffffffu, v1, 8);
            v2 += __shfl_xor_sync(0xffffffffu, v2, 8);
            float v = (lane & 8) ? v2 : v1;
            v += __shfl_xor_sync(0xffffffffu, v, 4);
            v += __shfl_xor_sync(0xffffffffu, v, 2);
            v += __shfl_xor_sync(0xffffffffu, v, 1);
            float h = c1r[j] + v;
            h = (h > 0.f) ? h : 0.01f * h;
            lg = fmaf(w2r[j], h, lg);
        }
        lg = (lg > 0.f) ? lg : 0.01f * lg;
        float w = (base + nsel < i1) ? __expf(lg) : 0.f;   // logits O(0.2): no max-sub
        float wA = __shfl_sync(0xffffffffu, w, 0);
        float wB = __shfl_sync(0xffffffffu, w, 16);
        float wC = __shfl_sync(0xffffffffu, w, 8);
        float wD = __shfl_sync(0xffffffffu, w, 24);
        Z += (wA + wB) + (wC + wD);
        ull wd;
        wd = f2pack(wA, wA);
        acc[0] = f2fma(wd, X[0][0], acc[0]); acc[1] = f2fma(wd, X[0][1], acc[1]);
        acc[2] = f2fma(wd, X[0][2], acc[2]); acc[3] = f2fma(wd, X[0][3], acc[3]);
        wd = f2pack(wB, wB);
        acc[0] = f2fma(wd, X[1][0], acc[0]); acc[1] = f2fma(wd, X[1][1], acc[1]);
        acc[2] = f2fma(wd, X[1][2], acc[2]); acc[3] = f2fma(wd, X[1][3], acc[3]);
        wd = f2pack(wC, wC);
        acc[0] = f2fma(wd, X[2][0], acc[0]); acc[1] = f2fma(wd, X[2][1], acc[1]);
        acc[2] = f2fma(wd, X[2][2], acc[2]); acc[3] = f2fma(wd, X[2][3], acc[3]);
        wd = f2pack(wD, wD);
        acc[0] = f2fma(wd, X[3][0], acc[0]); acc[1] = f2fma(wd, X[3][1], acc[1]);
        acc[2] = f2fma(wd, X[3][2], acc[2]); acc[3] = f2fma(wd, X[3][3], acc[3]);
    };

    int bgrp = i0 + wo * 4;                // this warp's first group; stride 16
    if (bgrp < i1) {
        LDGROUP(X0, bgrp);
        int b = bgrp;
        while (true) {
            if (b + 16 < i1) LDGROUP(X1, b + 16);
            process(X0, b);
            b += 16;
            if (b >= i1) break;
            if (b + 16 < i1) LDGROUP(X0, b + 16);
            process(X1, b);
            b += 16;
            if (b >= i1) break;
        }
    }
#undef LDGROUP

    // combine 4 warps
    float a0f, a1f, a2f, a3f, a4f, a5f, a6f, a7f;
    f2unpack(acc[0], a0f, a1f); f2unpack(acc[1], a2f, a3f);
    f2unpack(acc[2], a4f, a5f); f2unpack(acc[3], a6f, a7f);
    if (lane == 0) s_Z[wo] = Z;
    s_acc[wo][lane]      = make_float4(a0f, a1f, a2f, a3f);
    s_acc[wo][32 + lane] = make_float4(a4f, a5f, a6f, a7f);
    __syncthreads();
    if (tid < 64) {
        float Zt = s_Z[0] + s_Z[1] + s_Z[2] + s_Z[3];
        float invZ = (i1 > i0) ? (1.f / Zt) : 0.f;
        float4 v0 = s_acc[0][tid], v1 = s_acc[1][tid], v2 = s_acc[2][tid], v3 = s_acc[3][tid];
        float4 o;
        o.x = (v0.x + v1.x + v2.x + v3.x) * invZ;
        o.y = (v0.y + v1.y + v2.y + v3.y) * invZ;
        o.z = (v0.z + v1.z + v2.z + v3.z) * invZ;
        o.w = (v0.w + v1.w + v2.w + v3.w) * invZ;
        ((float4*)(d_Sdiv + (size_t)g * DD))[tid] = o;
        if (tid == 0) d_has[g] = (i1 > i0) ? 1.f : 0.f;
    }
}

// ---------------- K5: SGEMM pair, merged via blockIdx.z ----------------
// z=0: C=d_gi, A=d_Sdiv, B=d_Wcomb, bias=bih (+has*bmsgih)
// z=1: C=d_gh, A=gf,     B=Whh,    bias=bhh
// 64M x 128N tile, 4M x 8N per thread, 256 threads, 768 blocks total
// (5.2 waves -> halves tail quantization vs two 384-block launches).
// Inner k-loop software-pipelined by 1: LDS for k+1 issues before k's FMAs,
// hiding the 29-cyc LDS latency that capped issue at 35.4%.
__global__ void __launch_bounds__(256) k_gemm(const float* __restrict__ Agf,
                                              const float* __restrict__ Bwhh,
                                              const float* __restrict__ bias0,
                                              const float* __restrict__ bias1) {
    int mode = blockIdx.z;
    const float* A    = mode ? Agf  : d_Sdiv;
    const float* Bw   = mode ? Bwhh : d_Wcomb;
    const float* bias = mode ? bias1 : bias0;
    float* C = mode ? d_gh : d_gi;

    __shared__ float As[2][16][68];
    __shared__ float Bs[2][16][132];
    int bm = blockIdx.y * 64, bn = blockIdx.x * 128;
    int tid = threadIdx.x;
    int lrA = tid >> 2, lcA = (tid & 3) * 4;   // A: 64 rows x 16 k, 1 float4/thread
    int lrB = tid >> 1, lcB = (tid & 1) * 8;   // B: 128 rows x 16 k, 2 float4/thread
    int tx = tid & 15, ty = tid >> 4;          // 16x16 threads; 4 M x 8 N each

    ull acc[4][4];
#pragma unroll
    for (int i = 0; i < 4; i++)
#pragma unroll
        for (int j = 0; j < 4; j++) acc[i][j] = 0ull;

    float4 avr  = *(const float4*)(A  + (size_t)(bm + lrA) * DD + lcA);
    float4 bvr0 = *(const float4*)(Bw + (size_t)(bn + lrB) * DD + lcB);
    float4 bvr1 = *(const float4*)(Bw + (size_t)(bn + lrB) * DD + lcB + 4);

    As[0][lcA + 0][lrA] = avr.x; As[0][lcA + 1][lrA] = avr.y;
    As[0][lcA + 2][lrA] = avr.z; As[0][lcA + 3][lrA] = avr.w;
    Bs[0][lcB + 0][lrB] = bvr0.x; Bs[0][lcB + 1][lrB] = bvr0.y;
    Bs[0][lcB + 2][lrB] = bvr0.z; Bs[0][lcB + 3][lrB] = bvr0.w;
    Bs[0][lcB + 4][lrB] = bvr1.x; Bs[0][lcB + 5][lrB] = bvr1.y;
    Bs[0][lcB + 6][lrB] = bvr1.z; Bs[0][lcB + 7][lrB] = bvr1.w;
    __syncthreads();

    for (int s = 0; s < 16; s++) {
        if (s + 1 < 16) {   // global prefetch of next slab into the other buffer
            int k0 = (s + 1) * 16;
            avr  = *(const float4*)(A  + (size_t)(bm + lrA) * DD + k0 + lcA);
            bvr0 = *(const float4*)(Bw + (size_t)(bn + lrB) * DD + k0 + lcB);
            bvr1 = *(const float4*)(Bw + (size_t)(bn + lrB) * DD + k0 + lcB + 4);
            int nb = (s + 1) & 1;
            As[nb][lcA + 0][lrA] = avr.x; As[nb][lcA + 1][lrA] = avr.y;
            As[nb][lcA + 2][lrA] = avr.z; As[nb][lcA + 3][lrA] = avr.w;
            Bs[nb][lcB + 0][lrB] = bvr0.x; Bs[nb][lcB + 1][lrB] = bvr0.y;
            Bs[nb][lcB + 2][lrB] = bvr0.z; Bs[nb][lcB + 3][lrB] = bvr0.w;
            Bs[nb][lcB + 4][lrB] = bvr1.x; Bs[nb][lcB + 5][lrB] = bvr1.y;
            Bs[nb][lcB + 6][lrB] = bvr1.z; Bs[nb][lcB + 7][lrB] = bvr1.w;
        }
        int cb = s & 1;
        // register pipeline: preload k=0
        float4 ap      = *(const float4*)&As[cb][0][ty * 4];
        ulonglong2 bp0 = *(const ulonglong2*)&Bs[cb][0][tx * 4];
        ulonglong2 bp1 = *(const ulonglong2*)&Bs[cb][0][64 + tx * 4];
#pragma unroll
        for (int k = 0; k < 16; k++) {
            float4 apc = ap; ulonglong2 b0c = bp0, b1c = bp1;
            if (k + 1 < 16) {   // issue k+1's LDS before k's FMAs
                ap  = *(const float4*)&As[cb][k + 1][ty * 4];
                bp0 = *(const ulonglong2*)&Bs[cb][k + 1][tx * 4];
                bp1 = *(const ulonglong2*)&Bs[cb][k + 1][64 + tx * 4];
            }
            ull a0 = f2pack(apc.x, apc.x), a1 = f2pack(apc.y, apc.y);
            ull a2 = f2pack(apc.z, apc.z), a3 = f2pack(apc.w, apc.w);
            acc[0][0] = f2fma(a0, b0c.x, acc[0][0]); acc[0][1] = f2fma(a0, b0c.y, acc[0][1]);
            acc[0][2] = f2fma(a0, b1c.x, acc[0][2]); acc[0][3] = f2fma(a0, b1c.y, acc[0][3]);
            acc[1][0] = f2fma(a1, b0c.x, acc[1][0]); acc[1][1] = f2fma(a1, b0c.y, acc[1][1]);
            acc[1][2] = f2fma(a1, b1c.x, acc[1][2]); acc[1][3] = f2fma(a1, b1c.y, acc[1][3]);
            acc[2][0] = f2fma(a2, b0c.x, acc[2][0]); acc[2][1] = f2fma(a2, b0c.y, acc[2][1]);
            acc[2][2] = f2fma(a2, b1c.x, acc[2][2]); acc[2][3] = f2fma(a2, b1c.y, acc[2][3]);
            acc[3][0] = f2fma(a3, b0c.x, acc[3][0]); acc[3][1] = f2fma(a3, b0c.y, acc[3][1]);
            acc[3][2] = f2fma(a3, b1c.x, acc[3][2]); acc[3][3] = f2fma(a3, b1c.y, acc[3][3]);
        }
        __syncthreads();
    }

#pragma unroll
    for (int i = 0; i < 4; i++) {
        int m = bm + ty * 4 + i;
        float hv = mode ? 0.f : d_has[m];
#pragma unroll
        for (int jh = 0; jh < 2; jh++) {
            int n0 = bn + jh * 64 + tx * 4;
            float c0, c1, c2, c3;
            f2unpack(acc[i][jh * 2 + 0], c0, c1);
            f2unpack(acc[i][jh * 2 + 1], c2, c3);
            float4 o;
            o.x = c0 + bias[n0 + 0] + (mode ? 0.f : hv * d_bmsgih[n0 + 0]);
            o.y = c1 + bias[n0 + 1] + (mode ? 0.f : hv * d_bmsgih[n0 + 1]);
            o.z = c2 + bias[n0 + 2] + (mode ? 0.f : hv * d_bmsgih[n0 + 2]);
            o.w = c3 + bias[n0 + 3] + (mode ? 0.f : hv * d_bmsgih[n0 + 3]);
            *(float4*)(C + (size_t)m * TH + n0) = o;
        }
    }
}

// ---------------- K6: GRU gate combine (float4) ----------------
__global__ void k_gates(const float* __restrict__ gf, float* __restrict__ out) {
    int idx = blockIdx.x * blockDim.x + threadIdx.x;   // over BB*DD/4
    int g = idx >> 6, f4 = idx & 63;
    const float4* gi = (const float4*)(d_gi + (size_t)g * TH);
    const float4* gh = (const float4*)(d_gh + (size_t)g * TH);
    float4 ir = gi[f4],      iz = gi[64 + f4],  in_ = gi[128 + f4];
    float4 hr = gh[f4],      hz = gh[64 + f4],  hn  = gh[128 + f4];
    float4 gfv = ((const float4*)gf)[idx];
    float4 o;
    {
        float r = 1.f / (1.f + __expf(-(ir.x + hr.x)));
        float z = 1.f / (1.f + __expf(-(iz.x + hz.x)));
        float n = tanhf(in_.x + r * hn.x);
        o.x = (1.f - z) * n + z * gfv.x;
    }
    {
        float r = 1.f / (1.f + __expf(-(ir.y + hr.y)));
        float z = 1.f / (1.f + __expf(-(iz.y + hz.y)));
        float n = tanhf(in_.y + r * hn.y);
        o.y = (1.f - z) * n + z * gfv.y;
    }
    {
        float r = 1.f / (1.f + __expf(-(ir.z + hr.z)));
        float z = 1.f / (1.f + __expf(-(iz.z + hz.z)));
        float n = tanhf(in_.z + r * hn.z);
        o.z = (1.f - z) * n + z * gfv.z;
    }
    {
        float r = 1.f / (1.f + __expf(-(ir.w + hr.w)));
        float z = 1.f / (1.f + __expf(-(iz.w + hz.w)));
        float n = tanhf(in_.w + r * hn.w);
        o.w = (1.f - z) * n + z * gfv.w;
    }
    ((float4*)out)[idx] = o;
}

// ---------------- launch ----------------
// attn stays in the profiled 4th slot (stability check). Merged gemm runs
// after attn/bmsgih (deps: z=0 needs Sdiv/Wcomb/bmsgih; z=1 needs only inputs).
extern "C" void kernel_launch(void* const* d_in, const int* in_sizes, int n_in,
                              void* d_out, int out_size) {
    const float* node = (const float*)d_in[0];
    const float* gf   = (const float*)d_in[1];
    const int*   seg  = (const int*)d_in[2];     // JAX coerces int64 -> int32 (x64 disabled)
    const float* Wmsg = (const float*)d_in[3];
    const float* bmsg = (const float*)d_in[4];
    const float* Wl1  = (const float*)d_in[5];
    const float* bl1  = (const float*)d_in[6];
    const float* Wl2  = (const float*)d_in[7];
    const float* bl2  = (const float*)d_in[8];
    const float* Wih  = (const float*)d_in[9];
    const float* Whh  = (const float*)d_in[10];
    const float* bih  = (const float*)d_in[11];
    const float* bhh  = (const float*)d_in[12];
    float* out = (float*)d_out;

    k_segstart<<<(BB + 1 + 255) / 256, 256>>>(seg);
    k_c1<<<BB / 8, 256>>>(gf, Wl1, bl1);
    k_wcomb<<<TH / 4, 256>>>(Wih, Wmsg);
    k_attn<<<BB, 128>>>(node, Wl1, Wl2, bl2);          // 4th launch: profiled slot
    k_bmsgih<<<TH, 256>>>(Wih, bmsg);
    dim3 gg(TH / 128, BB / 64, 2);
    k_gemm<<<gg, 256>>>(gf, Whh, bih, bhh);
    k_gates<<<(BB * DD / 4) / 256, 256>>>(gf, out);
}

// round 17
// speedup vs baseline: 1.1105x; 1.1105x over previous
#include <cuda_runtime.h>

#define NN 500000
#define BB 4096
#define DD 256
#define DL 10
#define TH 768

typedef unsigned long long ull;

// ---------------- f32x2 packed-math helpers (sm_103a FFMA2 path) ----------------
__device__ __forceinline__ ull f2pack(float lo, float hi) {
    ull r; asm("mov.b64 %0, {%1, %2};" : "=l"(r) : "f"(lo), "f"(hi)); return r;
}
__device__ __forceinline__ void f2unpack(ull v, float& lo, float& hi) {
    asm("mov.b64 {%0, %1}, %2;" : "=f"(lo), "=f"(hi) : "l"(v));
}
__device__ __forceinline__ ull f2fma(ull a, ull b, ull c) {
    ull d; asm("fma.rn.f32x2 %0, %1, %2, %3;" : "=l"(d) : "l"(a), "l"(b), "l"(c)); return d;
}
__device__ __forceinline__ ull f2mul(ull a, ull b) {
    ull d; asm("mul.rn.f32x2 %0, %1, %2;" : "=l"(d) : "l"(a), "l"(b)); return d;
}

// ---------------- device scratch (no allocation allowed) ----------------
__device__ int   d_segstart[BB + 1];
__device__ float d_c1[BB * DL];          // graph-half of layer1 + b_l1, per graph
__device__ float d_Sdiv[BB * DD];        // softmax-weighted mean of node feats per graph
__device__ float d_has[BB];              // 1 if segment nonempty else 0
__device__ float d_Wcomb[TH * DD];       // W_ih @ W_msg
__device__ float d_bmsgih[TH];           // W_ih @ b_msg
__device__ float d_gi[(size_t)BB * TH];
__device__ float d_gh[(size_t)BB * TH];

// ---------------- K1: segment boundaries (ids are sorted, int32) ----------------
__global__ void k_segstart(const int* __restrict__ seg) {
    int g = blockIdx.x * blockDim.x + threadIdx.x;
    if (g > BB) return;
    int lo = 0, hi = NN;
    while (lo < hi) {
        int mid = (lo + hi) >> 1;
        if (seg[mid] < g) lo = mid + 1; else hi = mid;
    }
    d_segstart[g] = lo;
}

// ---------------- K2: c1[g][j] = W_l1[j, :256] . relu(gf[g]) + b_l1[j] ----------------
// Atomic-free: warp per graph, butterfly reduction.
__global__ void __launch_bounds__(256) k_c1(const float* __restrict__ gf,
                                            const float* __restrict__ Wl1,
                                            const float* __restrict__ bl1) {
    __shared__ float Wg[DL][260];    // graph-half of W_l1 (columns 0..255)
    __shared__ float bl[DL];
    int tid = threadIdx.x;
    int wo = tid >> 5, lane = tid & 31;
    for (int i = tid; i < DL * DD; i += 256) {
        int j = i >> 8, f = i & 255;
        Wg[j][f] = Wl1[j * (2 * DD) + f];
    }
    if (tid < DL) bl[tid] = bl1[tid];
    __syncthreads();

    int g = blockIdx.x * 8 + wo;
    const float4* gp = (const float4*)(gf + (size_t)g * DD);
    float4 a = gp[lane], b = gp[32 + lane];
    a.x = fmaxf(a.x, 0.f); a.y = fmaxf(a.y, 0.f); a.z = fmaxf(a.z, 0.f); a.w = fmaxf(a.w, 0.f);
    b.x = fmaxf(b.x, 0.f); b.y = fmaxf(b.y, 0.f); b.z = fmaxf(b.z, 0.f); b.w = fmaxf(b.w, 0.f);

    float p[DL];
#pragma unroll
    for (int j = 0; j < DL; j++) {
        float4 w0 = *(const float4*)&Wg[j][lane * 4];
        float4 w1 = *(const float4*)&Wg[j][128 + lane * 4];
        float s = w0.x * a.x;
        s = fmaf(w0.y, a.y, s); s = fmaf(w0.z, a.z, s); s = fmaf(w0.w, a.w, s);
        s = fmaf(w1.x, b.x, s); s = fmaf(w1.y, b.y, s);
        s = fmaf(w1.z, b.z, s); s = fmaf(w1.w, b.w, s);
        p[j] = s;
    }
#pragma unroll
    for (int off = 16; off; off >>= 1) {
#pragma unroll
        for (int j = 0; j < DL; j++) p[j] += __shfl_xor_sync(0xffffffffu, p[j], off);
    }
    if (lane == 0) {
#pragma unroll
        for (int j = 0; j < DL; j++) d_c1[g * DL + j] = p[j] + bl[j];
    }
}

// ---------------- K3: W_comb = W_ih @ W_msg  (768x256) ----------------
__global__ void k_wcomb(const float* __restrict__ Wih, const float* __restrict__ Wmsg) {
    __shared__ float wih_s[4][DD];
    int o0 = blockIdx.x * 4, t = threadIdx.x;
#pragma unroll
    for (int oo = 0; oo < 4; oo++) wih_s[oo][t] = Wih[(o0 + oo) * DD + t];
    __syncthreads();
    float a0 = 0.f, a1 = 0.f, a2 = 0.f, a3 = 0.f;
    for (int m = 0; m < DD; m++) {
        float wm = Wmsg[m * DD + t];
        a0 = fmaf(wih_s[0][m], wm, a0);
        a1 = fmaf(wih_s[1][m], wm, a1);
        a2 = fmaf(wih_s[2][m], wm, a2);
        a3 = fmaf(wih_s[3][m], wm, a3);
    }
    d_Wcomb[(o0 + 0) * DD + t] = a0;
    d_Wcomb[(o0 + 1) * DD + t] = a1;
    d_Wcomb[(o0 + 2) * DD + t] = a2;
    d_Wcomb[(o0 + 3) * DD + t] = a3;
}

// ---------------- K3b: bmsg_ih[o] = W_ih[o] . b_msg ----------------
__global__ void k_bmsgih(const float* __restrict__ Wih, const float* __restrict__ bmsg) {
    __shared__ float s;
    int o = blockIdx.x, t = threadIdx.x;
    if (t == 0) s = 0.f;
    __syncthreads();
    float v = Wih[o * DD + t] * bmsg[t];
#pragma unroll
    for (int off = 16; off; off >>= 1) v += __shfl_xor_sync(0xffffffffu, v, off);
    if ((t & 31) == 0) atomicAdd(&s, v);
    __syncthreads();
    if (t == 0) d_bmsgih[o] = s;
}

// ---------------- K4: fused attention + weighted segment mean ----------------
// R13 per-node structure (4-node groups, packed f32x2 dot, batched butterfly)
// but SINGLE-buffered (X1 ping-pong dropped: -32 regs) and c1/w2 read from
// smem in-loop (-20 regs), targeting 3 blocks = 12 warps/SM via
// __launch_bounds__(128,3). The exposed per-group LDG latency is covered by
// the extra co-resident warps + L2 prefetch two groups ahead (zero regs).
// R16 profile: 235 regs -> 8 warps/SM -> the 5-deep shuffle chain per j
// (~130cyc) had nothing to hide behind (issue 40.1%).
__global__ void __launch_bounds__(128, 3) k_attn(const float* __restrict__ xf,
                                                 const float* __restrict__ Wl1,
                                                 const float* __restrict__ Wl2,
                                                 const float* __restrict__ bl2) {
    __shared__ float Ws[DL][260];     // node-half of W_l1 (10x256, padded)
    __shared__ float c_s[DL];
    __shared__ float w2_s[DL];
    __shared__ float s_Z[4];
    __shared__ float4 s_acc[4][64];   // [warp][feature-float4]
    int tid = threadIdx.x;
    int wo = tid >> 5, lane = tid & 31;
    int g = blockIdx.x;

    for (int i = tid; i < DL * DD; i += 128) {
        int j = i >> 8, f = i & 255;
        Ws[j][f] = Wl1[j * (2 * DD) + DD + f];
    }
    if (tid < DL) { c_s[tid] = d_c1[g * DL + tid]; w2_s[tid] = Wl2[tid]; }
    __syncthreads();

    float b2v = bl2[0];
    int i0 = d_segstart[g], i1 = d_segstart[g + 1];

    ull acc[4] = {0ull, 0ull, 0ull, 0ull};   // packed 8-feature accumulator
    float Z = 0.f;
    int nsel = ((lane >> 3) & 1) * 2 + ((lane >> 4) & 1);  // 0..7->A 16..23->B 8..15->C 24..31->D

    ull X0[4][4];   // single group of 4 nodes, 8 packed floats each

#define LDGROUP(XR, BASE) do {                                                 \
    _Pragma("unroll")                                                          \
    for (int s_ = 0; s_ < 4; s_++) {                                           \
        int idx_ = (BASE) + s_;                                                \
        if (idx_ < i1) {                                                       \
            const ulonglong2* rp_ = (const ulonglong2*)(xf + (size_t)idx_ * DD); \
            ulonglong2 u_ = rp_[lane];                                         \
            ulonglong2 v_ = rp_[32 + lane];                                    \
            XR[s_][0] = u_.x; XR[s_][1] = u_.y;                                \
            XR[s_][2] = v_.x; XR[s_][3] = v_.y;                                \
        } else {                                                               \
            XR[s_][0] = 0ull; XR[s_][1] = 0ull;                                \
            XR[s_][2] = 0ull; XR[s_][3] = 0ull;                                \
        }                                                                      \
    } } while (0)

// L2 prefetch: 32 lanes cover 4 nodes x 8 lines (clamped; i1 > i0 here)
#define PFGROUP(BASE) do {                                                     \
    int pfi_ = (BASE) + (lane >> 3);                                           \
    if (pfi_ >= i1) pfi_ = i1 - 1;                                             \
    asm volatile("prefetch.global.L2 [%0];"                                    \
                 :: "l"(xf + (size_t)pfi_ * DD + (lane & 7) * 32));            \
    } while (0)

    auto process = [&](const ull (*X)[4], int base) {
        float lg = b2v;
#pragma unroll
        for (int j = 0; j < DL; j++) {
            ulonglong2 wv0 = *(const ulonglong2*)&Ws[j][lane * 4];
            ulonglong2 wv1 = *(const ulonglong2*)&Ws[j][128 + lane * 4];
            float pA, pB, pC, pD;
            {
                ull t0 = f2fma(wv0.y, X[0][1], f2mul(wv0.x, X[0][0]));
                t0 = f2fma(wv1.x, X[0][2], t0);
                t0 = f2fma(wv1.y, X[0][3], t0);
                float lo, hi; f2unpack(t0, lo, hi); pA = lo + hi;
                ull t1 = f2fma(wv0.y, X[1][1], f2mul(wv0.x, X[1][0]));
                t1 = f2fma(wv1.x, X[1][2], t1);
                t1 = f2fma(wv1.y, X[1][3], t1);
                f2unpack(t1, lo, hi); pB = lo + hi;
                ull t2 = f2fma(wv0.y, X[2][1], f2mul(wv0.x, X[2][0]));
                t2 = f2fma(wv1.x, X[2][2], t2);
                t2 = f2fma(wv1.y, X[2][3], t2);
                f2unpack(t2, lo, hi); pC = lo + hi;
                ull t3 = f2fma(wv0.y, X[3][1], f2mul(wv0.x, X[3][0]));
                t3 = f2fma(wv1.x, X[3][2], t3);
                t3 = f2fma(wv1.y, X[3][3], t3);
                f2unpack(t3, lo, hi); pD = lo + hi;
            }
            float ra = pA + __shfl_xor_sync(0xffffffffu, pA, 16);
            float rb = pB + __shfl_xor_sync(0xffffffffu, pB, 16);
            float rc = pC + __shfl_xor_sync(0xffffffffu, pC, 16);
            float rd = pD + __shfl_xor_sync(0xffffffffu, pD, 16);
            float v1 = (lane & 16) ? rb : ra;
            float v2 = (lane & 16) ? rd : rc;
            v1 += __shfl_xor_sync(0xffffffffu, v1, 8);
            v2 += __shfl_xor_sync(0xffffffffu, v2, 8);
            float v = (lane & 8) ? v2 : v1;
            v += __shfl_xor_sync(0xffffffffu, v, 4);
            v += __shfl_xor_sync(0xffffffffu, v, 2);
            v += __shfl_xor_sync(0xffffffffu, v, 1);
            float h = c_s[j] + v;
            h = (h > 0.f) ? h : 0.01f * h;
            lg = fmaf(w2_s[j], h, lg);
        }
        lg = (lg > 0.f) ? lg : 0.01f * lg;
        float w = (base + nsel < i1) ? __expf(lg) : 0.f;   // logits O(0.2): no max-sub
        float wA = __shfl_sync(0xffffffffu, w, 0);
        float wB = __shfl_sync(0xffffffffu, w, 16);
        float wC = __shfl_sync(0xffffffffu, w, 8);
        float wD = __shfl_sync(0xffffffffu, w, 24);
        Z += (wA + wB) + (wC + wD);
        ull wd;
        wd = f2pack(wA, wA);
        acc[0] = f2fma(wd, X[0][0], acc[0]); acc[1] = f2fma(wd, X[0][1], acc[1]);
        acc[2] = f2fma(wd, X[0][2], acc[2]); acc[3] = f2fma(wd, X[0][3], acc[3]);
        wd = f2pack(wB, wB);
        acc[0] = f2fma(wd, X[1][0], acc[0]); acc[1] = f2fma(wd, X[1][1], acc[1]);
        acc[2] = f2fma(wd, X[1][2], acc[2]); acc[3] = f2fma(wd, X[1][3], acc[3]);
        wd = f2pack(wC, wC);
        acc[0] = f2fma(wd, X[2][0], acc[0]); acc[1] = f2fma(wd, X[2][1], acc[1]);
        acc[2] = f2fma(wd, X[2][2], acc[2]); acc[3] = f2fma(wd, X[2][3], acc[3]);
        wd = f2pack(wD, wD);
        acc[0] = f2fma(wd, X[3][0], acc[0]); acc[1] = f2fma(wd, X[3][1], acc[1]);
        acc[2] = f2fma(wd, X[3][2], acc[2]); acc[3] = f2fma(wd, X[3][3], acc[3]);
    };

    for (int b = i0 + wo * 4; b < i1; b += 16) {
        LDGROUP(X0, b);
        if (b + 32 < i1) PFGROUP(b + 32);   // L2 prefetch two groups ahead
        process(X0, b);
    }
#undef LDGROUP
#undef PFGROUP

    // combine 4 warps
    float a0f, a1f, a2f, a3f, a4f, a5f, a6f, a7f;
    f2unpack(acc[0], a0f, a1f); f2unpack(acc[1], a2f, a3f);
    f2unpack(acc[2], a4f, a5f); f2unpack(acc[3], a6f, a7f);
    if (lane == 0) s_Z[wo] = Z;
    s_acc[wo][lane]      = make_float4(a0f, a1f, a2f, a3f);
    s_acc[wo][32 + lane] = make_float4(a4f, a5f, a6f, a7f);
    __syncthreads();
    if (tid < 64) {
        float Zt = s_Z[0] + s_Z[1] + s_Z[2] + s_Z[3];
        float invZ = (i1 > i0) ? (1.f / Zt) : 0.f;
        float4 v0 = s_acc[0][tid], v1 = s_acc[1][tid], v2 = s_acc[2][tid], v3 = s_acc[3][tid];
        float4 o;
        o.x = (v0.x + v1.x + v2.x + v3.x) * invZ;
        o.y = (v0.y + v1.y + v2.y + v3.y) * invZ;
        o.z = (v0.z + v1.z + v2.z + v3.z) * invZ;
        o.w = (v0.w + v1.w + v2.w + v3.w) * invZ;
        ((float4*)(d_Sdiv + (size_t)g * DD))[tid] = o;
        if (tid == 0) d_has[g] = (i1 > i0) ? 1.f : 0.f;
    }
}

// ---------------- K5: SGEMM pair, merged via blockIdx.z (R16, UNCHANGED) ----------------
__global__ void __launch_bounds__(256) k_gemm(const float* __restrict__ Agf,
                                              const float* __restrict__ Bwhh,
                                              const float* __restrict__ bias0,
                                              const float* __restrict__ bias1) {
    int mode = blockIdx.z;
    const float* A    = mode ? Agf  : d_Sdiv;
    const float* Bw   = mode ? Bwhh : d_Wcomb;
    const float* bias = mode ? bias1 : bias0;
    float* C = mode ? d_gh : d_gi;

    __shared__ float As[2][16][68];
    __shared__ float Bs[2][16][132];
    int bm = blockIdx.y * 64, bn = blockIdx.x * 128;
    int tid = threadIdx.x;
    int lrA = tid >> 2, lcA = (tid & 3) * 4;
    int lrB = tid >> 1, lcB = (tid & 1) * 8;
    int tx = tid & 15, ty = tid >> 4;

    ull acc[4][4];
#pragma unroll
    for (int i = 0; i < 4; i++)
#pragma unroll
        for (int j = 0; j < 4; j++) acc[i][j] = 0ull;

    float4 avr  = *(const float4*)(A  + (size_t)(bm + lrA) * DD + lcA);
    float4 bvr0 = *(const float4*)(Bw + (size_t)(bn + lrB) * DD + lcB);
    float4 bvr1 = *(const float4*)(Bw + (size_t)(bn + lrB) * DD + lcB + 4);

    As[0][lcA + 0][lrA] = avr.x; As[0][lcA + 1][lrA] = avr.y;
    As[0][lcA + 2][lrA] = avr.z; As[0][lcA + 3][lrA] = avr.w;
    Bs[0][lcB + 0][lrB] = bvr0.x; Bs[0][lcB + 1][lrB] = bvr0.y;
    Bs[0][lcB + 2][lrB] = bvr0.z; Bs[0][lcB + 3][lrB] = bvr0.w;
    Bs[0][lcB + 4][lrB] = bvr1.x; Bs[0][lcB + 5][lrB] = bvr1.y;
    Bs[0][lcB + 6][lrB] = bvr1.z; Bs[0][lcB + 7][lrB] = bvr1.w;
    __syncthreads();

    for (int s = 0; s < 16; s++) {
        if (s + 1 < 16) {
            int k0 = (s + 1) * 16;
            avr  = *(const float4*)(A  + (size_t)(bm + lrA) * DD + k0 + lcA);
            bvr0 = *(const float4*)(Bw + (size_t)(bn + lrB) * DD + k0 + lcB);
            bvr1 = *(const float4*)(Bw + (size_t)(bn + lrB) * DD + k0 + lcB + 4);
            int nb = (s + 1) & 1;
            As[nb][lcA + 0][lrA] = avr.x; As[nb][lcA + 1][lrA] = avr.y;
            As[nb][lcA + 2][lrA] = avr.z; As[nb][lcA + 3][lrA] = avr.w;
            Bs[nb][lcB + 0][lrB] = bvr0.x; Bs[nb][lcB + 1][lrB] = bvr0.y;
            Bs[nb][lcB + 2][lrB] = bvr0.z; Bs[nb][lcB + 3][lrB] = bvr0.w;
            Bs[nb][lcB + 4][lrB] = bvr1.x; Bs[nb][lcB + 5][lrB] = bvr1.y;
            Bs[nb][lcB + 6][lrB] = bvr1.z; Bs[nb][lcB + 7][lrB] = bvr1.w;
        }
        int cb = s & 1;
        float4 ap      = *(const float4*)&As[cb][0][ty * 4];
        ulonglong2 bp0 = *(const ulonglong2*)&Bs[cb][0][tx * 4];
        ulonglong2 bp1 = *(const ulonglong2*)&Bs[cb][0][64 + tx * 4];
#pragma unroll
        for (int k = 0; k < 16; k++) {
            float4 apc = ap; ulonglong2 b0c = bp0, b1c = bp1;
            if (k + 1 < 16) {
                ap  = *(const float4*)&As[cb][k + 1][ty * 4];
                bp0 = *(const ulonglong2*)&Bs[cb][k + 1][tx * 4];
                bp1 = *(const ulonglong2*)&Bs[cb][k + 1][64 + tx * 4];
            }
            ull a0 = f2pack(apc.x, apc.x), a1 = f2pack(apc.y, apc.y);
            ull a2 = f2pack(apc.z, apc.z), a3 = f2pack(apc.w, apc.w);
            acc[0][0] = f2fma(a0, b0c.x, acc[0][0]); acc[0][1] = f2fma(a0, b0c.y, acc[0][1]);
            acc[0][2] = f2fma(a0, b1c.x, acc[0][2]); acc[0][3] = f2fma(a0, b1c.y, acc[0][3]);
            acc[1][0] = f2fma(a1, b0c.x, acc[1][0]); acc[1][1] = f2fma(a1, b0c.y, acc[1][1]);
            acc[1][2] = f2fma(a1, b1c.x, acc[1][2]); acc[1][3] = f2fma(a1, b1c.y, acc[1][3]);
            acc[2][0] = f2fma(a2, b0c.x, acc[2][0]); acc[2][1] = f2fma(a2, b0c.y, acc[2][1]);
            acc[2][2] = f2fma(a2, b1c.x, acc[2][2]); acc[2][3] = f2fma(a2, b1c.y, acc[2][3]);
            acc[3][0] = f2fma(a3, b0c.x, acc[3][0]); acc[3][1] = f2fma(a3, b0c.y, acc[3][1]);
            acc[3][2] = f2fma(a3, b1c.x, acc[3][2]); acc[3][3] = f2fma(a3, b1c.y, acc[3][3]);
        }
        __syncthreads();
    }

#pragma unroll
    for (int i = 0; i < 4; i++) {
        int m = bm + ty * 4 + i;
        float hv = mode ? 0.f : d_has[m];
#pragma unroll
        for (int jh = 0; jh < 2; jh++) {
            int n0 = bn + jh * 64 + tx * 4;
            float c0, c1, c2, c3;
            f2unpack(acc[i][jh * 2 + 0], c0, c1);
            f2unpack(acc[i][jh * 2 + 1], c2, c3);
            float4 o;
            o.x = c0 + bias[n0 + 0] + (mode ? 0.f : hv * d_bmsgih[n0 + 0]);
            o.y = c1 + bias[n0 + 1] + (mode ? 0.f : hv * d_bmsgih[n0 + 1]);
            o.z = c2 + bias[n0 + 2] + (mode ? 0.f : hv * d_bmsgih[n0 + 2]);
            o.w = c3 + bias[n0 + 3] + (mode ? 0.f : hv * d_bmsgih[n0 + 3]);
            *(float4*)(C + (size_t)m * TH + n0) = o;
        }
    }
}

// ---------------- K6: GRU gate combine (float4) ----------------
__global__ void k_gates(const float* __restrict__ gf, float* __restrict__ out) {
    int idx = blockIdx.x * blockDim.x + threadIdx.x;   // over BB*DD/4
    int g = idx >> 6, f4 = idx & 63;
    const float4* gi = (const float4*)(d_gi + (size_t)g * TH);
    const float4* gh = (const float4*)(d_gh + (size_t)g * TH);
    float4 ir = gi[f4],      iz = gi[64 + f4],  in_ = gi[128 + f4];
    float4 hr = gh[f4],      hz = gh[64 + f4],  hn  = gh[128 + f4];
    float4 gfv = ((const float4*)gf)[idx];
    float4 o;
    {
        float r = 1.f / (1.f + __expf(-(ir.x + hr.x)));
        float z = 1.f / (1.f + __expf(-(iz.x + hz.x)));
        float n = tanhf(in_.x + r * hn.x);
        o.x = (1.f - z) * n + z * gfv.x;
    }
    {
        float r = 1.f / (1.f + __expf(-(ir.y + hr.y)));
        float z = 1.f / (1.f + __expf(-(iz.y + hz.y)));
        float n = tanhf(in_.y + r * hn.y);
        o.y = (1.f - z) * n + z * gfv.y;
    }
    {
        float r = 1.f / (1.f + __expf(-(ir.z + hr.z)));
        float z = 1.f / (1.f + __expf(-(iz.z + hz.z)));
        float n = tanhf(in_.z + r * hn.z);
        o.z = (1.f - z) * n + z * gfv.z;
    }
    {
        float r = 1.f / (1.f + __expf(-(ir.w + hr.w)));
        float z = 1.f / (1.f + __expf(-(iz.w + hz.w)));
        float n = tanhf(in_.w + r * hn.w);
        o.w = (1.f - z) * n + z * gfv.w;
    }
    ((float4*)out)[idx] = o;
}

// ---------------- launch ----------------
// attn in the profiled 4th slot to verify the occupancy fix.
extern "C" void kernel_launch(void* const* d_in, const int* in_sizes, int n_in,
                              void* d_out, int out_size) {
    const float* node = (const float*)d_in[0];
    const float* gf   = (const float*)d_in[1];
    const int*   seg  = (const int*)d_in[2];     // JAX coerces int64 -> int32 (x64 disabled)
    const float* Wmsg = (const float*)d_in[3];
    const float* bmsg = (const float*)d_in[4];
    const float* Wl1  = (const float*)d_in[5];
    const float* bl1  = (const float*)d_in[6];
    const float* Wl2  = (const float*)d_in[7];
    const float* bl2  = (const float*)d_in[8];
    const float* Wih  = (const float*)d_in[9];
    const float* Whh  = (const float*)d_in[10];
    const float* bih  = (const float*)d_in[11];
    const float* bhh  = (const float*)d_in[12];
    float* out = (float*)d_out;

    k_segstart<<<(BB + 1 + 255) / 256, 256>>>(seg);
    k_c1<<<BB / 8, 256>>>(gf, Wl1, bl1);
    k_wcomb<<<TH / 4, 256>>>(Wih, Wmsg);
    k_attn<<<BB, 128>>>(node, Wl1, Wl2, bl2);          // 4th launch: profiled slot
    k_bmsgih<<<TH, 256>>>(Wih, bmsg);
    dim3 gg(TH / 128, BB / 64, 2);
    k_gemm<<<gg, 256>>>(gf, Whh, bih, bhh);
    k_gates<<<(BB * DD / 4) / 256, 256>>>(gf, out);
}